// round 3
// baseline (speedup 1.0000x reference)
#include <cuda_runtime.h>
#include <cstdint>

// Problem constants (fixed by setup_inputs)
#define BB 8
#define NN 8192
#define NPOINT 1024
#define NSAMPLE 32
#define DD 64
#define R2 0.0625f
#define OUTCH 67  // 3 + 64

#define CLUSTER 4
#define FPS_THREADS 512
#define PTS_CTA (NN / CLUSTER)   // 2048 points per CTA, 4 per thread

using u64 = unsigned long long;

// ---- packed f32x2 helpers (per-lane IEEE RN, bit-identical to scalar RN ops)
__device__ __forceinline__ u64 pk2(float lo, float hi) {
    u64 r; asm("mov.b64 %0, {%1,%2};" : "=l"(r) : "f"(lo), "f"(hi)); return r;
}
__device__ __forceinline__ void up2(u64 v, float& lo, float& hi) {
    asm("mov.b64 {%0,%1}, %2;" : "=f"(lo), "=f"(hi) : "l"(v));
}
__device__ __forceinline__ u64 add2(u64 a, u64 b) {
    u64 r; asm("add.rn.f32x2 %0, %1, %2;" : "=l"(r) : "l"(a), "l"(b)); return r;
}
__device__ __forceinline__ u64 mul2(u64 a, u64 b) {
    u64 r; asm("mul.rn.f32x2 %0, %1, %2;" : "=l"(r) : "l"(a), "l"(b)); return r;
}

__device__ __forceinline__ uint32_t smem_u32(const void* p) {
    uint32_t a;
    asm("{ .reg .u64 t; cvta.to.shared.u64 t, %1; cvt.u32.u64 %0, t; }"
        : "=r"(a) : "l"(p));
    return a;
}
__device__ __forceinline__ uint32_t mapa_u32(uint32_t a, uint32_t rank) {
    uint32_t o; asm("mapa.shared::cluster.u32 %0, %1, %2;" : "=r"(o) : "r"(a), "r"(rank));
    return o;
}

#define MBAR_INIT(addr, cnt) \
    asm volatile("mbarrier.init.shared.b64 [%0], %1;" :: "r"(addr), "r"(cnt) : "memory")

#define MBAR_WAIT_ACQ_CLUSTER(addr, parity) do {                                  \
    asm volatile("{\n\t.reg .pred P;\n\t"                                         \
                 "W%=:\n\t"                                                       \
                 "mbarrier.try_wait.parity.acquire.cluster.shared::cta.b64 P, [%0], %1, 0x989680;\n\t" \
                 "@!P bra W%=;\n\t}"                                              \
                 :: "r"(addr), "r"(parity) : "memory");                           \
} while (0)

struct __align__(16) Slot {
    unsigned val;   // float bits of max dist (nonneg -> u32 monotonic)
    unsigned idx;   // global point index (tie-break: smaller wins)
    float    x, y, z;
    unsigned pad[3];
};  // 32 bytes

// ---------------------------------------------------------------------------
// Kernel 0: pack {x, y, z, |p|^2} per point into a device scratch (float4).
// |p|^2 uses the reference einsum/sum order: ((x*x + y*y) + z*z), RN each step.
// ---------------------------------------------------------------------------
__device__ float4 g_pk[BB * NN];

__global__ void prep_kernel(const float* __restrict__ xyz) {
    int i = blockIdx.x * blockDim.x + threadIdx.x;   // 0 .. BB*NN-1
    const float* p = xyz + (size_t)i * 3;
    float x = __ldg(p + 0), y = __ldg(p + 1), z = __ldg(p + 2);
    float dn = __fadd_rn(__fadd_rn(__fmul_rn(x, x), __fmul_rn(y, y)),
                         __fmul_rn(z, z));
    g_pk[i] = make_float4(x, y, z, dn);
}

// ---------------------------------------------------------------------------
// Kernel 1: farthest point sampling. One 4-CTA cluster per batch, 512 threads
// per CTA, 4 points/thread held in packed f32x2 registers. Per step:
//  - packed exact distance update (sub as add-of-neg, bit-identical)
//  - warp argmax: REDUX.max on value bits, then REDUX.min on matching global
//    index (jnp.argmax first-occurrence tie-break)
//  - block argmax in warp0 over 16 warp results
//  - cross-CTA: warp0 lanes 0..3 push {val, idx, x, y, z} + release-arrive to
//    every CTA's DSMEM slot; all threads acquire-wait the parity mbarrier and
//    select the cluster winner from 4 slots. Coordinates travel with the key,
//    so no dependent global load sits on the critical path.
// Slots are double-buffered by step parity (protocol-safe, see analysis).
// ---------------------------------------------------------------------------
__global__ void __launch_bounds__(FPS_THREADS, 1) __cluster_dims__(CLUSTER, 1, 1)
fps_kernel(const float* __restrict__ xyz, float* __restrict__ new_xyz) {
    const int tid  = threadIdx.x;
    const int lane = tid & 31;
    const int w    = tid >> 5;
    const unsigned rank = blockIdx.x & (CLUSTER - 1);     // == cluster_ctarank
    const int b    = blockIdx.x / CLUSTER;
    const int base = rank * PTS_CTA;

    const float* xb = xyz + (size_t)b * NN * 3;

    __shared__ unsigned sw_val[16];
    __shared__ unsigned sw_idx[16];
    __shared__ float4   sw_coord[16];
    __shared__ Slot     ex[2][CLUSTER];
    __shared__ u64      mbar;

    const uint32_t mb_a = smem_u32(&mbar);
    if (tid == 0) MBAR_INIT(mb_a, CLUSTER);
    // make mbarrier init visible cluster-wide before any remote arrive
    asm volatile("barrier.cluster.arrive.aligned;" ::: "memory");
    asm volatile("barrier.cluster.wait.aligned;"   ::: "memory");

    // per-lane remote addresses (lanes 0..3 of warp0 use them)
    const uint32_t ex_a   = smem_u32(&ex[0][0]);
    const unsigned tgt    = lane & (CLUSTER - 1);
    const uint32_t rs0    = mapa_u32(ex_a + (0 * CLUSTER + rank) * 32u, tgt);
    const uint32_t rs1    = mapa_u32(ex_a + (1 * CLUSTER + rank) * 32u, tgt);
    const uint32_t rmb    = mapa_u32(mb_a, tgt);

    // load 4 points (k = 0..3), pack pairs (0,1) and (2,3)
    u64 px2[2], py2[2], pz2[2];
    float d0 = 1e10f, d1 = 1e10f, d2 = 1e10f, d3 = 1e10f;
    {
        int j0 = base + tid, j1 = j0 + 512, j2 = j0 + 1024, j3 = j0 + 1536;
        px2[0] = pk2(__ldg(xb + j0 * 3 + 0), __ldg(xb + j1 * 3 + 0));
        py2[0] = pk2(__ldg(xb + j0 * 3 + 1), __ldg(xb + j1 * 3 + 1));
        pz2[0] = pk2(__ldg(xb + j0 * 3 + 2), __ldg(xb + j1 * 3 + 2));
        px2[1] = pk2(__ldg(xb + j2 * 3 + 0), __ldg(xb + j3 * 3 + 0));
        py2[1] = pk2(__ldg(xb + j2 * 3 + 1), __ldg(xb + j3 * 3 + 1));
        pz2[1] = pk2(__ldg(xb + j2 * 3 + 2), __ldg(xb + j3 * 3 + 2));
    }

    // step-0 centroid = xyz[b][0]
    float cx = __ldg(xb + 0), cy = __ldg(xb + 1), cz = __ldg(xb + 2);

    float* ob = new_xyz + (size_t)b * NPOINT * 3;
    const u64 SGN = 0x8000000080000000ull;

    for (int it = 0; it < NPOINT; it++) {
        if (rank == 0 && tid == 0) {
            ob[it * 3 + 0] = cx; ob[it * 3 + 1] = cy; ob[it * 3 + 2] = cz;
        }
        if (it == NPOINT - 1) break;

        const u64 ncx = pk2(cx, cx) ^ SGN;
        const u64 ncy = pk2(cy, cy) ^ SGN;
        const u64 ncz = pk2(cz, cz) ^ SGN;

        // exact jnp order: d = ((dx*dx + dy*dy) + dz*dz); dist = min(dist, d)
        {
            u64 dx = add2(px2[0], ncx), dy = add2(py2[0], ncy), dz = add2(pz2[0], ncz);
            u64 dd = add2(add2(mul2(dx, dx), mul2(dy, dy)), mul2(dz, dz));
            float a, bq; up2(dd, a, bq);
            d0 = fminf(d0, a); d1 = fminf(d1, bq);
        }
        {
            u64 dx = add2(px2[1], ncx), dy = add2(py2[1], ncy), dz = add2(pz2[1], ncz);
            u64 dd = add2(add2(mul2(dx, dx), mul2(dy, dy)), mul2(dz, dz));
            float a, bq; up2(dd, a, bq);
            d2 = fminf(d2, a); d3 = fminf(d3, bq);
        }
        float vmax = fmaxf(fmaxf(d0, d1), fmaxf(d2, d3));
        unsigned vb = __float_as_uint(vmax);

        // warp argmax: value, then min matching global index
        unsigned wmax = __reduce_max_sync(0xffffffffu, vb);
        unsigned cand = 0xffffffffu;
        int ck = 0;
        if (vb == wmax) {   // scan k descending -> final = smallest k = smallest idx
            if (__float_as_uint(d3) == wmax) { cand = base + tid + 1536; ck = 3; }
            if (__float_as_uint(d2) == wmax) { cand = base + tid + 1024; ck = 2; }
            if (__float_as_uint(d1) == wmax) { cand = base + tid + 512;  ck = 1; }
            if (__float_as_uint(d0) == wmax) { cand = base + tid;        ck = 0; }
        }
        unsigned ci = __reduce_min_sync(0xffffffffu, cand);

        if (lane == 0) { sw_val[w] = wmax; sw_idx[w] = ci; }
        if (cand == ci && cand != 0xffffffffu) {   // unique winner thread of warp w
            float x0, x1, x2, x3, y0, y1, y2, y3, z0, z1, z2, z3;
            up2(px2[0], x0, x1); up2(px2[1], x2, x3);
            up2(py2[0], y0, y1); up2(py2[1], y2, y3);
            up2(pz2[0], z0, z1); up2(pz2[1], z2, z3);
            float xx = (ck & 2) ? ((ck & 1) ? x3 : x2) : ((ck & 1) ? x1 : x0);
            float yy = (ck & 2) ? ((ck & 1) ? y3 : y2) : ((ck & 1) ? y1 : y0);
            float zz = (ck & 2) ? ((ck & 1) ? z3 : z2) : ((ck & 1) ? z1 : z0);
            sw_coord[w] = make_float4(xx, yy, zz, 0.0f);
        }
        __syncthreads();

        if (tid < 32) {
            unsigned v  = (lane < 16) ? sw_val[lane] : 0u;
            unsigned bm = __reduce_max_sync(0xffffffffu, v);
            unsigned c2 = (lane < 16 && v == bm) ? sw_idx[lane] : 0xffffffffu;
            unsigned bi = __reduce_min_sync(0xffffffffu, c2);
            unsigned bal = __ballot_sync(0xffffffffu, c2 == bi);
            int ws = __ffs(bal) - 1;
            float4 co = sw_coord[ws];     // same-address broadcast
            if (lane < CLUSTER) {
                uint32_t dst = (it & 1) ? rs1 : rs0;
                asm volatile("st.shared::cluster.v4.b32 [%0], {%1,%2,%3,%4};"
                             :: "r"(dst), "r"(bm), "r"(bi),
                                "r"(__float_as_uint(co.x)), "r"(__float_as_uint(co.y))
                             : "memory");
                asm volatile("st.shared::cluster.b32 [%0], %1;"
                             :: "r"(dst + 16u), "r"(__float_as_uint(co.z)) : "memory");
                asm volatile("mbarrier.arrive.release.cluster.shared::cluster.b64 _, [%0];"
                             :: "r"(rmb) : "memory");
            }
        }

        MBAR_WAIT_ACQ_CLUSTER(mb_a, (unsigned)(it & 1));

        // cluster winner among 4 slots: max val, tie -> min idx
        const Slot* S = ex[it & 1];
        unsigned bv = S[0].val, bi = S[0].idx;
        float bx = S[0].x, by = S[0].y, bz = S[0].z;
#pragma unroll
        for (int s = 1; s < CLUSTER; s++) {
            unsigned tv = S[s].val, ti = S[s].idx;
            float tx = S[s].x, ty = S[s].y, tz = S[s].z;
            bool better = (tv > bv) || (tv == bv && ti < bi);
            if (better) { bv = tv; bi = ti; bx = tx; by = ty; bz = tz; }
        }
        cx = bx; cy = by; cz = bz;
    }
}

// ---------------------------------------------------------------------------
// Kernel 2: ball query + gather + concat. One warp per centroid, 8 warps/CTA.
// Points staged through smem as packed {x,y,z,|p|^2} float4 tiles (coalesced
// LDG.128 loads from the prep scratch, single LDS.128 per scanned point).
// Selection = first 32 indices with d<=r^2 in index order; pad with first.
// ---------------------------------------------------------------------------
#define TILE 1024
__global__ void __launch_bounds__(256)
ball_kernel(const float* __restrict__ points,
            const float* __restrict__ new_xyz, float* __restrict__ new_points) {
    __shared__ float4 sxyz[TILE];     // 16 KB
    __shared__ int sel[8][NSAMPLE];

    const int tid  = threadIdx.x;
    const int w    = tid >> 5;
    const int lane = tid & 31;
    const int gw   = blockIdx.x * 8 + w;    // centroid id
    const int b    = gw >> 10;
    const int m    = gw & (NPOINT - 1);

    const float4* pk = g_pk + (size_t)b * NN;
    const float* c  = new_xyz + ((size_t)b * NPOINT + m) * 3;
    const float sx = c[0], sy = c[1], sz = c[2];
    const float sn = __fadd_rn(__fadd_rn(__fmul_rn(sx, sx), __fmul_rn(sy, sy)),
                               __fmul_rn(sz, sz));

    int cnt = 0;
    bool done = false;
    for (int t = 0; t < NN / TILE; t++) {
        if (__syncthreads_and(done ? 1 : 0)) break;
        {   // cooperative coalesced tile load: 1024 float4, 4 per thread
            const float4* src = pk + t * TILE;
            sxyz[tid]       = __ldg(src + tid);
            sxyz[tid + 256] = __ldg(src + tid + 256);
            sxyz[tid + 512] = __ldg(src + tid + 512);
            sxyz[tid + 768] = __ldg(src + tid + 768);
        }
        __syncthreads();
        if (!done) {
            for (int base = 0; base < TILE; base += 32) {
                float4 v = sxyz[base + lane];
                // sqr = (-2*dot + |src|^2) + |dst|^2, dot = ((sx*x+sy*y)+sz*z)
                float dot = __fadd_rn(__fadd_rn(__fmul_rn(sx, v.x), __fmul_rn(sy, v.y)),
                                      __fmul_rn(sz, v.z));
                float q = __fadd_rn(__fadd_rn(__fmul_rn(-2.0f, dot), sn), v.w);
                bool ok = (q <= R2);
                unsigned msk = __ballot_sync(0xffffffffu, ok);
                if (ok) {
                    int p = cnt + __popc(msk & ((1u << lane) - 1u));
                    if (p < NSAMPLE) sel[w][p] = t * TILE + base + lane;
                }
                cnt += __popc(msk);
                if (cnt >= NSAMPLE) { done = true; break; }
            }
        }
    }
    __syncwarp();

    // pad with first qualifying index (centroid itself always qualifies)
    int cfull = cnt < NSAMPLE ? cnt : NSAMPLE;
    int first = sel[w][0];
    __syncwarp();
    if (lane >= cfull) sel[w][lane] = first;
    __syncwarp();

    float* op = new_points + ((size_t)(b * NPOINT + m)) * NSAMPLE * OUTCH;

    // centered xyz: one LDG.128 per lane's own sample
    {
        const int idx = sel[w][lane];
        float4 v = __ldg(pk + idx);
        op[lane * OUTCH + 0] = __fsub_rn(v.x, sx);
        op[lane * OUTCH + 1] = __fsub_rn(v.y, sy);
        op[lane * OUTCH + 2] = __fsub_rn(v.z, sz);
    }

    // features: per sample the warp reads one 256B row coalesced, writes 64
    // consecutive floats (2 per lane)
    const float* pb = points + (size_t)b * NN * DD;
#pragma unroll 4
    for (int s = 0; s < NSAMPLE; s++) {
        int is = sel[w][s];                       // smem broadcast
        float2 v = __ldg((const float2*)(pb + (size_t)is * DD) + lane);
        op[s * OUTCH + 3 + 2 * lane]     = v.x;
        op[s * OUTCH + 3 + 2 * lane + 1] = v.y;
    }
}

// ---------------------------------------------------------------------------
extern "C" void kernel_launch(void* const* d_in, const int* in_sizes, int n_in,
                              void* d_out, int out_size) {
    const float* xyz    = (const float*)d_in[0];
    const float* points = (const float*)d_in[1];

    float* new_xyz    = (float*)d_out;
    float* new_points = (float*)d_out + (size_t)BB * NPOINT * 3;

    prep_kernel<<<(BB * NN) / 256, 256>>>(xyz);
    fps_kernel<<<BB * CLUSTER, FPS_THREADS>>>(xyz, new_xyz);
    ball_kernel<<<(BB * NPOINT) / 8, 256>>>(points, new_xyz, new_points);
}

// round 5
// speedup vs baseline: 1.5765x; 1.5765x over previous
#include <cuda_runtime.h>
#include <cstdint>

// Problem constants (fixed by setup_inputs)
#define BB 8
#define NN 8192
#define NPOINT 1024
#define NSAMPLE 32
#define DD 64
#define R2 0.0625f
#define OUTCH 67  // 3 + 64

using u64 = unsigned long long;
using u32 = unsigned int;

// ---- packed f32x2 helpers (per-lane IEEE RN, bit-identical to scalar RN ops)
__device__ __forceinline__ u64 pk2(float lo, float hi) {
    u64 r; asm("mov.b64 %0, {%1,%2};" : "=l"(r) : "f"(lo), "f"(hi)); return r;
}
__device__ __forceinline__ void up2(u64 v, float& lo, float& hi) {
    asm("mov.b64 {%0,%1}, %2;" : "=f"(lo), "=f"(hi) : "l"(v));
}
__device__ __forceinline__ u64 add2(u64 a, u64 b) {
    u64 r; asm("add.rn.f32x2 %0, %1, %2;" : "=l"(r) : "l"(a), "l"(b)); return r;
}
__device__ __forceinline__ u64 mul2(u64 a, u64 b) {
    u64 r; asm("mul.rn.f32x2 %0, %1, %2;" : "=l"(r) : "l"(a), "l"(b)); return r;
}

// ---------------------------------------------------------------------------
// Scratch: packed {x, y, z, |p|^2} per point (written by prep blocks fused
// into the FPS launch; consumed by ball_kernel).
// ---------------------------------------------------------------------------
__device__ float4 g_pk[BB * NN];

// ---------------------------------------------------------------------------
// Fused kernel: blocks 0..7 run FPS (one CTA per batch, 1024 threads, 8
// points/thread in packed f32x2 registers, batch xyz staged in 96KB dynamic
// smem). Blocks 8..71 run the pack-prep for ball_kernel on otherwise idle SMs.
//
// FPS per step:
//  - packed exact distance update (sub as add-of-neg; bit-identical to jnp's
//    ((dx*dx + dy*dy) + dz*dz) with RN at every op)
//  - dist kept as u32 bit patterns (nonneg floats: unsigned order == float
//    order). min-update, max-tree and argmax tree are ALU-pipe integer ops.
//    Argmax tree prefers the left operand on '>=', i.e. smallest k, i.e.
//    smallest global index  == jnp.argmax first-occurrence tie-break.
//  - warp: REDUX.max(value) then REDUX.min(matching index); lane0 packs
//    (val<<32 | ~idx) into smem (32 warps -> 32 keys).
//  - warp0: 32 keys -> REDUX.max on hi, REDUX.max on masked ~idx -> sh_f.
//  - all threads: f = sh_f; centroid = 3 broadcast LDS from the smem copy.
// ---------------------------------------------------------------------------
__global__ void __launch_bounds__(1024, 1)
fps_prep_kernel(const float* __restrict__ xyz, float* __restrict__ new_xyz) {
    const int tid = threadIdx.x;

    if (blockIdx.x >= BB) {
        // ---- prep path: pack {x,y,z,|p|^2}; |p|^2 in reference order
        int i = (blockIdx.x - BB) * 1024 + tid;      // 0 .. BB*NN-1
        const float* p = xyz + (size_t)i * 3;
        float x = __ldg(p + 0), y = __ldg(p + 1), z = __ldg(p + 2);
        float dn = __fadd_rn(__fadd_rn(__fmul_rn(x, x), __fmul_rn(y, y)),
                             __fmul_rn(z, z));
        g_pk[i] = make_float4(x, y, z, dn);
        return;
    }

    // ---- FPS path
    extern __shared__ float sxyz[];                  // [NN*3] = 96KB
    __shared__ u64 sw_key[32];
    __shared__ int sh_f;

    const int b    = blockIdx.x;
    const int lane = tid & 31;
    const int w    = tid >> 5;
    const float* xb = xyz + (size_t)b * NN * 3;

    // stage batch xyz into smem (6144 float4 = 6 per thread, coalesced)
    {
        const float4* src = (const float4*)xb;
        float4* dst = (float4*)sxyz;
#pragma unroll
        for (int i = 0; i < 6; i++) dst[tid + i * 1024] = __ldg(src + tid + i * 1024);
    }

    // per-thread points: k=0..7 at global index tid + k*1024, packed by pairs
    u64 px2[4], py2[4], pz2[4];
    u32 du[8];
#pragma unroll
    for (int p = 0; p < 4; p++) {
        int j0 = tid + (2 * p) * 1024, j1 = tid + (2 * p + 1) * 1024;
        px2[p] = pk2(__ldg(xb + j0 * 3 + 0), __ldg(xb + j1 * 3 + 0));
        py2[p] = pk2(__ldg(xb + j0 * 3 + 1), __ldg(xb + j1 * 3 + 1));
        pz2[p] = pk2(__ldg(xb + j0 * 3 + 2), __ldg(xb + j1 * 3 + 2));
    }
#pragma unroll
    for (int k = 0; k < 8; k++) du[k] = __float_as_uint(1e10f);

    __syncthreads();   // smem xyz ready

    float cx = sxyz[0], cy = sxyz[1], cz = sxyz[2];  // first centroid = idx 0
    float* ob = new_xyz + (size_t)b * NPOINT * 3;
    const u64 SGN = 0x8000000080000000ull;

    for (int it = 0; it < NPOINT; it++) {
        if (tid == 0) {
            ob[it * 3 + 0] = cx; ob[it * 3 + 1] = cy; ob[it * 3 + 2] = cz;
        }
        if (it == NPOINT - 1) break;

        const u64 ncx = pk2(cx, cx) ^ SGN;
        const u64 ncy = pk2(cy, cy) ^ SGN;
        const u64 ncz = pk2(cz, cz) ^ SGN;

        // exact jnp order: d = ((dx*dx + dy*dy) + dz*dz); dist = min(dist, d)
#pragma unroll
        for (int p = 0; p < 4; p++) {
            u64 dx = add2(px2[p], ncx);
            u64 dy = add2(py2[p], ncy);
            u64 dz = add2(pz2[p], ncz);
            u64 dd = add2(add2(mul2(dx, dx), mul2(dy, dy)), mul2(dz, dz));
            float a, bq; up2(dd, a, bq);
            du[2 * p]     = min(du[2 * p],     __float_as_uint(a));
            du[2 * p + 1] = min(du[2 * p + 1], __float_as_uint(bq));
        }

        // per-thread argmax tree (ALU). '>=' keeps left -> smallest k on ties.
        u32 v01 = max(du[0], du[1]); int k01 = (du[0] >= du[1]) ? 0 : 1;
        u32 v23 = max(du[2], du[3]); int k23 = (du[2] >= du[3]) ? 2 : 3;
        u32 v45 = max(du[4], du[5]); int k45 = (du[4] >= du[5]) ? 4 : 5;
        u32 v67 = max(du[6], du[7]); int k67 = (du[6] >= du[7]) ? 6 : 7;
        u32 v03 = max(v01, v23);     int k03 = (v01 >= v23) ? k01 : k23;
        u32 v47 = max(v45, v67);     int k47 = (v45 >= v67) ? k45 : k67;
        u32 vb  = max(v03, v47);     int kk  = (v03 >= v47) ? k03 : k47;
        u32 idx = (u32)(tid + kk * 1024);

        // warp reduce: max value, then min index among holders of the max
        u32 wmax = __reduce_max_sync(0xffffffffu, vb);
        u32 cand = (vb == wmax) ? idx : 0xffffffffu;
        u32 ci   = __reduce_min_sync(0xffffffffu, cand);
        if (lane == 0) sw_key[w] = ((u64)wmax << 32) | (u32)(~ci);
        __syncthreads();

        if (tid < 32) {
            u64 key = sw_key[lane];                 // all 32 warps' keys
            u32 khi = (u32)(key >> 32), klo = (u32)key;
            u32 mhi = __reduce_max_sync(0xffffffffu, khi);
            u32 mlo = __reduce_max_sync(0xffffffffu, (khi == mhi) ? klo : 0u);
            if (lane == 0) sh_f = (int)(~mlo);
        }
        __syncthreads();

        const int f = sh_f;
        cx = sxyz[f * 3 + 0]; cy = sxyz[f * 3 + 1]; cz = sxyz[f * 3 + 2];
    }
}

// ---------------------------------------------------------------------------
// Kernel 2: ball query + gather + concat. One warp per centroid, 8 warps/CTA.
// Points staged through smem as packed {x,y,z,|p|^2} float4 tiles (coalesced
// LDG.128 loads from the prep scratch, single LDS.128 per scanned point).
// Selection = first 32 indices with d<=r^2 in index order; pad with first.
// ---------------------------------------------------------------------------
#define TILE 1024
__global__ void __launch_bounds__(256)
ball_kernel(const float* __restrict__ points,
            const float* __restrict__ new_xyz, float* __restrict__ new_points) {
    __shared__ float4 sxyz[TILE];     // 16 KB
    __shared__ int sel[8][NSAMPLE];

    const int tid  = threadIdx.x;
    const int w    = tid >> 5;
    const int lane = tid & 31;
    const int gw   = blockIdx.x * 8 + w;    // centroid id
    const int b    = gw >> 10;
    const int m    = gw & (NPOINT - 1);

    const float4* pk = g_pk + (size_t)b * NN;
    const float* c  = new_xyz + ((size_t)b * NPOINT + m) * 3;
    const float sx = c[0], sy = c[1], sz = c[2];
    const float sn = __fadd_rn(__fadd_rn(__fmul_rn(sx, sx), __fmul_rn(sy, sy)),
                               __fmul_rn(sz, sz));

    int cnt = 0;
    bool done = false;
    for (int t = 0; t < NN / TILE; t++) {
        if (__syncthreads_and(done ? 1 : 0)) break;
        {   // cooperative coalesced tile load: 1024 float4, 4 per thread
            const float4* src = pk + t * TILE;
            sxyz[tid]       = __ldg(src + tid);
            sxyz[tid + 256] = __ldg(src + tid + 256);
            sxyz[tid + 512] = __ldg(src + tid + 512);
            sxyz[tid + 768] = __ldg(src + tid + 768);
        }
        __syncthreads();
        if (!done) {
            for (int base = 0; base < TILE; base += 32) {
                float4 v = sxyz[base + lane];
                // sqr = (-2*dot + |src|^2) + |dst|^2, dot = ((sx*x+sy*y)+sz*z)
                float dot = __fadd_rn(__fadd_rn(__fmul_rn(sx, v.x), __fmul_rn(sy, v.y)),
                                      __fmul_rn(sz, v.z));
                float q = __fadd_rn(__fadd_rn(__fmul_rn(-2.0f, dot), sn), v.w);
                bool ok = (q <= R2);
                unsigned msk = __ballot_sync(0xffffffffu, ok);
                if (ok) {
                    int p = cnt + __popc(msk & ((1u << lane) - 1u));
                    if (p < NSAMPLE) sel[w][p] = t * TILE + base + lane;
                }
                cnt += __popc(msk);
                if (cnt >= NSAMPLE) { done = true; break; }
            }
        }
    }
    __syncwarp();

    // pad with first qualifying index (centroid itself always qualifies)
    int cfull = cnt < NSAMPLE ? cnt : NSAMPLE;
    int first = sel[w][0];
    __syncwarp();
    if (lane >= cfull) sel[w][lane] = first;
    __syncwarp();

    float* op = new_points + ((size_t)(b * NPOINT + m)) * NSAMPLE * OUTCH;

    // centered xyz: one LDG.128 per lane's own sample
    {
        const int idx = sel[w][lane];
        float4 v = __ldg(pk + idx);
        op[lane * OUTCH + 0] = __fsub_rn(v.x, sx);
        op[lane * OUTCH + 1] = __fsub_rn(v.y, sy);
        op[lane * OUTCH + 2] = __fsub_rn(v.z, sz);
    }

    // features: per sample the warp reads one 256B row coalesced, writes 64
    // consecutive floats (2 per lane)
    const float* pb = points + (size_t)b * NN * DD;
#pragma unroll 4
    for (int s = 0; s < NSAMPLE; s++) {
        int is = sel[w][s];                       // smem broadcast
        float2 v = __ldg((const float2*)(pb + (size_t)is * DD) + lane);
        op[s * OUTCH + 3 + 2 * lane]     = v.x;
        op[s * OUTCH + 3 + 2 * lane + 1] = v.y;
    }
}

// ---------------------------------------------------------------------------
extern "C" void kernel_launch(void* const* d_in, const int* in_sizes, int n_in,
                              void* d_out, int out_size) {
    const float* xyz    = (const float*)d_in[0];
    const float* points = (const float*)d_in[1];

    float* new_xyz    = (float*)d_out;
    float* new_points = (float*)d_out + (size_t)BB * NPOINT * 3;

    const int smem = NN * 3 * sizeof(float);   // 96 KB
    cudaFuncSetAttribute(fps_prep_kernel,
                         cudaFuncAttributeMaxDynamicSharedMemorySize, smem);

    // blocks 0..7: FPS (one per batch); blocks 8..71: pack-prep on idle SMs
    fps_prep_kernel<<<BB + (BB * NN) / 1024, 1024, smem>>>(xyz, new_xyz);
    ball_kernel<<<(BB * NPOINT) / 8, 256>>>(points, new_xyz, new_points);
}

// round 6
// speedup vs baseline: 1.6560x; 1.0504x over previous
#include <cuda_runtime.h>
#include <cstdint>

// Problem constants (fixed by setup_inputs)
#define BB 8
#define NN 8192
#define NPOINT 1024
#define NSAMPLE 32
#define DD 64
#define R2 0.0625f
#define OUTCH 67  // 3 + 64

using u64 = unsigned long long;
using u32 = unsigned int;

// ---- packed f32x2 helpers (per-lane IEEE RN, bit-identical to scalar RN ops)
__device__ __forceinline__ u64 pk2(float lo, float hi) {
    u64 r; asm("mov.b64 %0, {%1,%2};" : "=l"(r) : "f"(lo), "f"(hi)); return r;
}
__device__ __forceinline__ void up2(u64 v, float& lo, float& hi) {
    asm("mov.b64 {%0,%1}, %2;" : "=f"(lo), "=f"(hi) : "l"(v));
}
__device__ __forceinline__ u64 add2(u64 a, u64 b) {
    u64 r; asm("add.rn.f32x2 %0, %1, %2;" : "=l"(r) : "l"(a), "l"(b)); return r;
}
__device__ __forceinline__ u64 mul2(u64 a, u64 b) {
    u64 r; asm("mul.rn.f32x2 %0, %1, %2;" : "=l"(r) : "l"(a), "l"(b)); return r;
}

// ---------------------------------------------------------------------------
// Scratch: packed {x, y, z, |p|^2} per point (written by prep blocks fused
// into the FPS launch; consumed by ball_kernel).
// ---------------------------------------------------------------------------
__device__ float4 g_pk[BB * NN];

// ---------------------------------------------------------------------------
// Fused kernel: blocks 0..7 run FPS (one CTA per batch, 1024 threads, 8
// points/thread in packed f32x2 registers). Blocks 8..71 run the pack-prep
// for ball_kernel on otherwise idle SMs.
//
// FPS design (per step, ONE barrier):
//  - centroid fetched as pre-negated, pre-duplicated packed u64 triple from a
//    192KB smem table (3 broadcast LDS.64; no per-step LOP3/MOV sign flips)
//  - packed exact distance update d = ((dx*dx + dy*dy) + dz*dz), every op RN,
//    subtraction realized as add of exact negation -> bit-identical to jnp
//  - dist kept as u32 bit patterns (nonneg floats: u32 order == float order);
//    min-update + argmax tree are ALU integer ops; tree prefers left on '>='
//    => smallest k => smallest global index == jnp.argmax first-occurrence
//  - warp: REDUX.max(value), REDUX.min(index); lane0 posts (val<<32 | ~idx)
//    into a parity-double-buffered key array
//  - after ONE __syncthreads, EVERY warp redundantly reduces the 32 keys and
//    computes f locally (no second barrier, no warp0 serialization)
// ---------------------------------------------------------------------------
__global__ void __launch_bounds__(1024, 1)
fps_prep_kernel(const float* __restrict__ xyz, float* __restrict__ new_xyz) {
    const int tid = threadIdx.x;

    if (blockIdx.x >= BB) {
        // ---- prep path: pack {x,y,z,|p|^2}; |p|^2 in reference order
        int i = (blockIdx.x - BB) * 1024 + tid;      // 0 .. BB*NN-1
        const float* p = xyz + (size_t)i * 3;
        float x = __ldg(p + 0), y = __ldg(p + 1), z = __ldg(p + 2);
        float dn = __fadd_rn(__fadd_rn(__fmul_rn(x, x), __fmul_rn(y, y)),
                             __fmul_rn(z, z));
        g_pk[i] = make_float4(x, y, z, dn);
        return;
    }

    // ---- FPS path
    extern __shared__ u64 sneg[];                 // [NN*3] = 192KB, negated dup
    __shared__ u64 sw_key[2][32];

    const int b    = blockIdx.x;
    const int lane = tid & 31;
    const int w    = tid >> 5;
    const float* xb = xyz + (size_t)b * NN * 3;

    // stage: load 8 points/thread; keep in packed registers AND write the
    // negated duplicated smem table
    u64 px2[4], py2[4], pz2[4];
    u32 du[8];
#pragma unroll
    for (int p = 0; p < 4; p++) {
        int j0 = tid + (2 * p) * 1024, j1 = tid + (2 * p + 1) * 1024;
        float x0 = __ldg(xb + j0 * 3 + 0), y0 = __ldg(xb + j0 * 3 + 1), z0 = __ldg(xb + j0 * 3 + 2);
        float x1 = __ldg(xb + j1 * 3 + 0), y1 = __ldg(xb + j1 * 3 + 1), z1 = __ldg(xb + j1 * 3 + 2);
        px2[p] = pk2(x0, x1); py2[p] = pk2(y0, y1); pz2[p] = pk2(z0, z1);
        sneg[3 * j0 + 0] = pk2(-x0, -x0);
        sneg[3 * j0 + 1] = pk2(-y0, -y0);
        sneg[3 * j0 + 2] = pk2(-z0, -z0);
        sneg[3 * j1 + 0] = pk2(-x1, -x1);
        sneg[3 * j1 + 1] = pk2(-y1, -y1);
        sneg[3 * j1 + 2] = pk2(-z1, -z1);
    }
#pragma unroll
    for (int k = 0; k < 8; k++) du[k] = __float_as_uint(1e10f);

    __syncthreads();   // smem table ready

    u64 ncx = sneg[0], ncy = sneg[1], ncz = sneg[2];   // centroid 0, negated
    float* ob = new_xyz + (size_t)b * NPOINT * 3;

    for (int it = 0; it < NPOINT; it++) {
        if (tid == 0) {   // emit un-negated centroid (sign XOR: exact)
            float lx, t0, ly, t1, lz, t2;
            up2(ncx, lx, t0); up2(ncy, ly, t1); up2(ncz, lz, t2);
            ob[it * 3 + 0] = __uint_as_float(__float_as_uint(lx) ^ 0x80000000u);
            ob[it * 3 + 1] = __uint_as_float(__float_as_uint(ly) ^ 0x80000000u);
            ob[it * 3 + 2] = __uint_as_float(__float_as_uint(lz) ^ 0x80000000u);
        }
        if (it == NPOINT - 1) break;

        // exact jnp order: d = ((dx*dx + dy*dy) + dz*dz); dist = min(dist, d)
#pragma unroll
        for (int p = 0; p < 4; p++) {
            u64 dx = add2(px2[p], ncx);
            u64 dy = add2(py2[p], ncy);
            u64 dz = add2(pz2[p], ncz);
            u64 dd = add2(add2(mul2(dx, dx), mul2(dy, dy)), mul2(dz, dz));
            float a, bq; up2(dd, a, bq);
            du[2 * p]     = min(du[2 * p],     __float_as_uint(a));
            du[2 * p + 1] = min(du[2 * p + 1], __float_as_uint(bq));
        }

        // per-thread argmax tree (ALU). '>=' keeps left -> smallest k on ties.
        u32 v01 = max(du[0], du[1]); int k01 = (du[0] >= du[1]) ? 0 : 1;
        u32 v23 = max(du[2], du[3]); int k23 = (du[2] >= du[3]) ? 2 : 3;
        u32 v45 = max(du[4], du[5]); int k45 = (du[4] >= du[5]) ? 4 : 5;
        u32 v67 = max(du[6], du[7]); int k67 = (du[6] >= du[7]) ? 6 : 7;
        u32 v03 = max(v01, v23);     int k03 = (v01 >= v23) ? k01 : k23;
        u32 v47 = max(v45, v67);     int k47 = (v45 >= v67) ? k45 : k67;
        u32 vb  = max(v03, v47);     int kk  = (v03 >= v47) ? k03 : k47;
        u32 idx = (u32)(tid + kk * 1024);

        // warp reduce: max value, then min index among holders of the max
        u32 wmax = __reduce_max_sync(0xffffffffu, vb);
        u32 cand = (vb == wmax) ? idx : 0xffffffffu;
        u32 ci   = __reduce_min_sync(0xffffffffu, cand);
        if (lane == 0) sw_key[it & 1][w] = ((u64)wmax << 32) | (u32)(~ci);
        __syncthreads();   // the ONLY barrier in the step

        // every warp reduces all 32 keys itself (no second barrier needed;
        // keys are parity-double-buffered so next step's posts can't clobber)
        u64 key = sw_key[it & 1][lane];
        u32 khi = (u32)(key >> 32), klo = (u32)key;
        u32 mhi = __reduce_max_sync(0xffffffffu, khi);
        u32 mlo = __reduce_max_sync(0xffffffffu, (khi == mhi) ? klo : 0u);
        const int f = (int)(~mlo);

        ncx = sneg[3 * f + 0];   // broadcast LDS.64
        ncy = sneg[3 * f + 1];
        ncz = sneg[3 * f + 2];
    }
}

// ---------------------------------------------------------------------------
// Kernel 2: ball query + gather + concat. One warp per centroid, 8 warps/CTA.
// Points staged through smem as packed {x,y,z,|p|^2} float4 tiles (coalesced
// LDG.128 loads from the prep scratch, single LDS.128 per scanned point).
// Selection = first 32 indices with d<=r^2 in index order; pad with first.
// ---------------------------------------------------------------------------
#define TILE 1024
__global__ void __launch_bounds__(256)
ball_kernel(const float* __restrict__ points,
            const float* __restrict__ new_xyz, float* __restrict__ new_points) {
    __shared__ float4 sxyz[TILE];     // 16 KB
    __shared__ int sel[8][NSAMPLE];

    const int tid  = threadIdx.x;
    const int w    = tid >> 5;
    const int lane = tid & 31;
    const int gw   = blockIdx.x * 8 + w;    // centroid id
    const int b    = gw >> 10;
    const int m    = gw & (NPOINT - 1);

    const float4* pk = g_pk + (size_t)b * NN;
    const float* c  = new_xyz + ((size_t)b * NPOINT + m) * 3;
    const float sx = c[0], sy = c[1], sz = c[2];
    const float sn = __fadd_rn(__fadd_rn(__fmul_rn(sx, sx), __fmul_rn(sy, sy)),
                               __fmul_rn(sz, sz));

    int cnt = 0;
    bool done = false;
    for (int t = 0; t < NN / TILE; t++) {
        if (__syncthreads_and(done ? 1 : 0)) break;
        {   // cooperative coalesced tile load: 1024 float4, 4 per thread
            const float4* src = pk + t * TILE;
            sxyz[tid]       = __ldg(src + tid);
            sxyz[tid + 256] = __ldg(src + tid + 256);
            sxyz[tid + 512] = __ldg(src + tid + 512);
            sxyz[tid + 768] = __ldg(src + tid + 768);
        }
        __syncthreads();
        if (!done) {
            for (int base = 0; base < TILE; base += 32) {
                float4 v = sxyz[base + lane];
                // sqr = (-2*dot + |src|^2) + |dst|^2, dot = ((sx*x+sy*y)+sz*z)
                float dot = __fadd_rn(__fadd_rn(__fmul_rn(sx, v.x), __fmul_rn(sy, v.y)),
                                      __fmul_rn(sz, v.z));
                float q = __fadd_rn(__fadd_rn(__fmul_rn(-2.0f, dot), sn), v.w);
                bool ok = (q <= R2);
                unsigned msk = __ballot_sync(0xffffffffu, ok);
                if (ok) {
                    int p = cnt + __popc(msk & ((1u << lane) - 1u));
                    if (p < NSAMPLE) sel[w][p] = t * TILE + base + lane;
                }
                cnt += __popc(msk);
                if (cnt >= NSAMPLE) { done = true; break; }
            }
        }
    }
    __syncwarp();

    // pad with first qualifying index (centroid itself always qualifies)
    int cfull = cnt < NSAMPLE ? cnt : NSAMPLE;
    int first = sel[w][0];
    __syncwarp();
    if (lane >= cfull) sel[w][lane] = first;
    __syncwarp();

    float* op = new_points + ((size_t)(b * NPOINT + m)) * NSAMPLE * OUTCH;

    // centered xyz: one LDG.128 per lane's own sample
    {
        const int idx = sel[w][lane];
        float4 v = __ldg(pk + idx);
        op[lane * OUTCH + 0] = __fsub_rn(v.x, sx);
        op[lane * OUTCH + 1] = __fsub_rn(v.y, sy);
        op[lane * OUTCH + 2] = __fsub_rn(v.z, sz);
    }

    // features: per sample the warp reads one 256B row coalesced, writes 64
    // consecutive floats (2 per lane)
    const float* pb = points + (size_t)b * NN * DD;
#pragma unroll 4
    for (int s = 0; s < NSAMPLE; s++) {
        int is = sel[w][s];                       // smem broadcast
        float2 v = __ldg((const float2*)(pb + (size_t)is * DD) + lane);
        op[s * OUTCH + 3 + 2 * lane]     = v.x;
        op[s * OUTCH + 3 + 2 * lane + 1] = v.y;
    }
}

// ---------------------------------------------------------------------------
extern "C" void kernel_launch(void* const* d_in, const int* in_sizes, int n_in,
                              void* d_out, int out_size) {
    const float* xyz    = (const float*)d_in[0];
    const float* points = (const float*)d_in[1];

    float* new_xyz    = (float*)d_out;
    float* new_points = (float*)d_out + (size_t)BB * NPOINT * 3;

    const int smem = NN * 3 * sizeof(u64);   // 192 KB negated-dup table
    cudaFuncSetAttribute(fps_prep_kernel,
                         cudaFuncAttributeMaxDynamicSharedMemorySize, smem);

    // blocks 0..7: FPS (one per batch); blocks 8..71: pack-prep on idle SMs
    fps_prep_kernel<<<BB + (BB * NN) / 1024, 1024, smem>>>(xyz, new_xyz);
    ball_kernel<<<(BB * NPOINT) / 8, 256>>>(points, new_xyz, new_points);
}

// round 7
// speedup vs baseline: 1.7099x; 1.0326x over previous
#include <cuda_runtime.h>
#include <cstdint>

// Problem constants (fixed by setup_inputs)
#define BB 8
#define NN 8192
#define NPOINT 1024
#define NSAMPLE 32
#define DD 64
#define R2 0.0625f
#define OUTCH 67  // 3 + 64

#define FPS_T 512          // FPS threads per CTA
#define PPT 16             // points per thread (8 packed pairs)

using u64 = unsigned long long;
using u32 = unsigned int;

// ---- packed f32x2 helpers (per-lane IEEE RN, bit-identical to scalar RN ops)
__device__ __forceinline__ u64 pk2(float lo, float hi) {
    u64 r; asm("mov.b64 %0, {%1,%2};" : "=l"(r) : "f"(lo), "f"(hi)); return r;
}
__device__ __forceinline__ void up2(u64 v, float& lo, float& hi) {
    asm("mov.b64 {%0,%1}, %2;" : "=f"(lo), "=f"(hi) : "l"(v));
}
__device__ __forceinline__ u64 add2(u64 a, u64 b) {
    u64 r; asm("add.rn.f32x2 %0, %1, %2;" : "=l"(r) : "l"(a), "l"(b)); return r;
}
__device__ __forceinline__ u64 mul2(u64 a, u64 b) {
    u64 r; asm("mul.rn.f32x2 %0, %1, %2;" : "=l"(r) : "l"(a), "l"(b)); return r;
}

// ---------------------------------------------------------------------------
// Scratch: packed {x, y, z, |p|^2} per point (written by prep blocks fused
// into the FPS launch; consumed by ball_kernel).
// ---------------------------------------------------------------------------
__device__ float4 g_pk[BB * NN];

// ---------------------------------------------------------------------------
// Fused kernel: blocks 0..7 run FPS (one CTA per batch, 512 threads, 16
// points/thread in packed f32x2 registers). Blocks 8..135 run the pack-prep
// for ball_kernel on otherwise idle SMs.
//
// FPS design (per step, ONE barrier). Rationale: the packed-fma distance
// update contributes a split-invariant 256 issue slots/SMSP, while ALL other
// per-thread costs scale with warps/SMSP. 512 threads x 16 pts/thread halves
// the per-SMSP overhead vs 1024x8.
//  - centroid fetched as pre-negated, pre-duplicated packed u64 triple from a
//    192KB smem table (3 broadcast LDS.64)
//  - packed exact distance update d = ((dx*dx + dy*dy) + dz*dz), every op RN,
//    subtraction realized as add of exact negation -> bit-identical to jnp
//  - dist kept as u32 bit patterns (nonneg floats: u32 order == float order);
//    15-node argmax tree prefers left on '>=' => smallest k => smallest
//    global index (idx = tid + k*512) == jnp.argmax first-occurrence
//  - warp: REDUX.max(value), REDUX.min(index); lane0 posts (val<<32 | ~idx)
//    into a parity-double-buffered 16-entry key array
//  - after ONE __syncthreads, EVERY warp redundantly reduces the 16 keys
//    (lanes mirror via lane&15) and computes f locally
// ---------------------------------------------------------------------------
__global__ void __launch_bounds__(FPS_T, 1)
fps_prep_kernel(const float* __restrict__ xyz, float* __restrict__ new_xyz) {
    const int tid = threadIdx.x;

    if (blockIdx.x >= BB) {
        // ---- prep path: pack {x,y,z,|p|^2}; |p|^2 in reference order
        int i = (blockIdx.x - BB) * FPS_T + tid;     // 0 .. BB*NN-1
        const float* p = xyz + (size_t)i * 3;
        float x = __ldg(p + 0), y = __ldg(p + 1), z = __ldg(p + 2);
        float dn = __fadd_rn(__fadd_rn(__fmul_rn(x, x), __fmul_rn(y, y)),
                             __fmul_rn(z, z));
        g_pk[i] = make_float4(x, y, z, dn);
        return;
    }

    // ---- FPS path
    extern __shared__ u64 sneg[];                 // [NN*3] = 192KB, negated dup
    __shared__ u64 sw_key[2][16];

    const int b    = blockIdx.x;
    const int lane = tid & 31;
    const int w    = tid >> 5;
    const float* xb = xyz + (size_t)b * NN * 3;

    // stage: load 16 points/thread; keep in packed registers AND write the
    // negated duplicated smem table
    u64 px2[8], py2[8], pz2[8];
    u32 du[PPT];
#pragma unroll
    for (int p = 0; p < 8; p++) {
        int j0 = tid + (2 * p) * FPS_T, j1 = tid + (2 * p + 1) * FPS_T;
        float x0 = __ldg(xb + j0 * 3 + 0), y0 = __ldg(xb + j0 * 3 + 1), z0 = __ldg(xb + j0 * 3 + 2);
        float x1 = __ldg(xb + j1 * 3 + 0), y1 = __ldg(xb + j1 * 3 + 1), z1 = __ldg(xb + j1 * 3 + 2);
        px2[p] = pk2(x0, x1); py2[p] = pk2(y0, y1); pz2[p] = pk2(z0, z1);
        sneg[3 * j0 + 0] = pk2(-x0, -x0);
        sneg[3 * j0 + 1] = pk2(-y0, -y0);
        sneg[3 * j0 + 2] = pk2(-z0, -z0);
        sneg[3 * j1 + 0] = pk2(-x1, -x1);
        sneg[3 * j1 + 1] = pk2(-y1, -y1);
        sneg[3 * j1 + 2] = pk2(-z1, -z1);
    }
#pragma unroll
    for (int k = 0; k < PPT; k++) du[k] = __float_as_uint(1e10f);

    __syncthreads();   // smem table ready

    u64 ncx = sneg[0], ncy = sneg[1], ncz = sneg[2];   // centroid 0, negated
    float* ob = new_xyz + (size_t)b * NPOINT * 3;

    for (int it = 0; it < NPOINT; it++) {
        if (tid == 0) {   // emit un-negated centroid (sign XOR: exact)
            float lx, t0, ly, t1, lz, t2;
            up2(ncx, lx, t0); up2(ncy, ly, t1); up2(ncz, lz, t2);
            ob[it * 3 + 0] = __uint_as_float(__float_as_uint(lx) ^ 0x80000000u);
            ob[it * 3 + 1] = __uint_as_float(__float_as_uint(ly) ^ 0x80000000u);
            ob[it * 3 + 2] = __uint_as_float(__float_as_uint(lz) ^ 0x80000000u);
        }
        if (it == NPOINT - 1) break;

        // exact jnp order: d = ((dx*dx + dy*dy) + dz*dz); dist = min(dist, d)
#pragma unroll
        for (int p = 0; p < 8; p++) {
            u64 dx = add2(px2[p], ncx);
            u64 dy = add2(py2[p], ncy);
            u64 dz = add2(pz2[p], ncz);
            u64 dd = add2(add2(mul2(dx, dx), mul2(dy, dy)), mul2(dz, dz));
            float a, bq; up2(dd, a, bq);
            du[2 * p]     = min(du[2 * p],     __float_as_uint(a));
            du[2 * p + 1] = min(du[2 * p + 1], __float_as_uint(bq));
        }

        // per-thread argmax tree over 16 (ALU). '>=' keeps left -> smallest k.
        u32 v[8]; int ki[8];
#pragma unroll
        for (int i = 0; i < 8; i++) {
            v[i]  = max(du[2 * i], du[2 * i + 1]);
            ki[i] = (du[2 * i] >= du[2 * i + 1]) ? 2 * i : 2 * i + 1;
        }
#pragma unroll
        for (int i = 0; i < 4; i++) {
            ki[i] = (v[2 * i] >= v[2 * i + 1]) ? ki[2 * i] : ki[2 * i + 1];
            v[i]  = max(v[2 * i], v[2 * i + 1]);
        }
        u32 v01 = max(v[0], v[1]); int k01 = (v[0] >= v[1]) ? ki[0] : ki[1];
        u32 v23 = max(v[2], v[3]); int k23 = (v[2] >= v[3]) ? ki[2] : ki[3];
        u32 vb  = max(v01, v23);   int kk  = (v01 >= v23) ? k01 : k23;
        u32 idx = (u32)(tid + kk * FPS_T);

        // warp reduce: max value, then min index among holders of the max
        u32 wmax = __reduce_max_sync(0xffffffffu, vb);
        u32 cand = (vb == wmax) ? idx : 0xffffffffu;
        u32 ci   = __reduce_min_sync(0xffffffffu, cand);
        if (lane == 0) sw_key[it & 1][w] = ((u64)wmax << 32) | (u32)(~ci);
        __syncthreads();   // the ONLY barrier in the step

        // every warp reduces the 16 keys itself (lanes mirror via lane&15;
        // parity double-buffer closes the cross-step race)
        u64 key = sw_key[it & 1][lane & 15];
        u32 khi = (u32)(key >> 32), klo = (u32)key;
        u32 mhi = __reduce_max_sync(0xffffffffu, khi);
        u32 mlo = __reduce_max_sync(0xffffffffu, (khi == mhi) ? klo : 0u);
        const int f = (int)(~mlo);

        ncx = sneg[3 * f + 0];   // broadcast LDS.64
        ncy = sneg[3 * f + 1];
        ncz = sneg[3 * f + 2];
    }
}

// ---------------------------------------------------------------------------
// Kernel 2: ball query + gather + concat. One warp per centroid, 8 warps/CTA.
// Points staged through smem as packed {x,y,z,|p|^2} float4 tiles (coalesced
// LDG.128 loads from the prep scratch, single LDS.128 per scanned point).
// Selection = first 32 indices with d<=r^2 in index order; pad with first.
// ---------------------------------------------------------------------------
#define TILE 1024
__global__ void __launch_bounds__(256)
ball_kernel(const float* __restrict__ points,
            const float* __restrict__ new_xyz, float* __restrict__ new_points) {
    __shared__ float4 sxyz[TILE];     // 16 KB
    __shared__ int sel[8][NSAMPLE];

    const int tid  = threadIdx.x;
    const int w    = tid >> 5;
    const int lane = tid & 31;
    const int gw   = blockIdx.x * 8 + w;    // centroid id
    const int b    = gw >> 10;
    const int m    = gw & (NPOINT - 1);

    const float4* pk = g_pk + (size_t)b * NN;
    const float* c  = new_xyz + ((size_t)b * NPOINT + m) * 3;
    const float sx = c[0], sy = c[1], sz = c[2];
    const float sn = __fadd_rn(__fadd_rn(__fmul_rn(sx, sx), __fmul_rn(sy, sy)),
                               __fmul_rn(sz, sz));

    int cnt = 0;
    bool done = false;
    for (int t = 0; t < NN / TILE; t++) {
        if (__syncthreads_and(done ? 1 : 0)) break;
        {   // cooperative coalesced tile load: 1024 float4, 4 per thread
            const float4* src = pk + t * TILE;
            sxyz[tid]       = __ldg(src + tid);
            sxyz[tid + 256] = __ldg(src + tid + 256);
            sxyz[tid + 512] = __ldg(src + tid + 512);
            sxyz[tid + 768] = __ldg(src + tid + 768);
        }
        __syncthreads();
        if (!done) {
            for (int base = 0; base < TILE; base += 32) {
                float4 v = sxyz[base + lane];
                // sqr = (-2*dot + |src|^2) + |dst|^2, dot = ((sx*x+sy*y)+sz*z)
                float dot = __fadd_rn(__fadd_rn(__fmul_rn(sx, v.x), __fmul_rn(sy, v.y)),
                                      __fmul_rn(sz, v.z));
                float q = __fadd_rn(__fadd_rn(__fmul_rn(-2.0f, dot), sn), v.w);
                bool ok = (q <= R2);
                unsigned msk = __ballot_sync(0xffffffffu, ok);
                if (ok) {
                    int p = cnt + __popc(msk & ((1u << lane) - 1u));
                    if (p < NSAMPLE) sel[w][p] = t * TILE + base + lane;
                }
                cnt += __popc(msk);
                if (cnt >= NSAMPLE) { done = true; break; }
            }
        }
    }
    __syncwarp();

    // pad with first qualifying index (centroid itself always qualifies)
    int cfull = cnt < NSAMPLE ? cnt : NSAMPLE;
    int first = sel[w][0];
    __syncwarp();
    if (lane >= cfull) sel[w][lane] = first;
    __syncwarp();

    float* op = new_points + ((size_t)(b * NPOINT + m)) * NSAMPLE * OUTCH;

    // centered xyz: one LDG.128 per lane's own sample
    {
        const int idx = sel[w][lane];
        float4 v = __ldg(pk + idx);
        op[lane * OUTCH + 0] = __fsub_rn(v.x, sx);
        op[lane * OUTCH + 1] = __fsub_rn(v.y, sy);
        op[lane * OUTCH + 2] = __fsub_rn(v.z, sz);
    }

    // features: per sample the warp reads one 256B row coalesced, writes 64
    // consecutive floats (2 per lane)
    const float* pb = points + (size_t)b * NN * DD;
#pragma unroll 4
    for (int s = 0; s < NSAMPLE; s++) {
        int is = sel[w][s];                       // smem broadcast
        float2 v = __ldg((const float2*)(pb + (size_t)is * DD) + lane);
        op[s * OUTCH + 3 + 2 * lane]     = v.x;
        op[s * OUTCH + 3 + 2 * lane + 1] = v.y;
    }
}

// ---------------------------------------------------------------------------
extern "C" void kernel_launch(void* const* d_in, const int* in_sizes, int n_in,
                              void* d_out, int out_size) {
    const float* xyz    = (const float*)d_in[0];
    const float* points = (const float*)d_in[1];

    float* new_xyz    = (float*)d_out;
    float* new_points = (float*)d_out + (size_t)BB * NPOINT * 3;

    const int smem = NN * 3 * sizeof(u64);   // 192 KB negated-dup table
    cudaFuncSetAttribute(fps_prep_kernel,
                         cudaFuncAttributeMaxDynamicSharedMemorySize, smem);

    // blocks 0..7: FPS (one per batch); blocks 8..135: pack-prep on idle SMs
    fps_prep_kernel<<<BB + (BB * NN) / FPS_T, FPS_T, smem>>>(xyz, new_xyz);
    ball_kernel<<<(BB * NPOINT) / 8, 256>>>(points, new_xyz, new_points);
}